// round 8
// baseline (speedup 1.0000x reference)
#include <cuda_runtime.h>
#include <math_constants.h>

// Problem constants
#define K_CODES 1024
#define C_DIM   256
#define N_PIX   32768
#define ZQ_ELEMS 8388608       // 32*256*32*32

// Tiling
#define TM 32                  // pixels per tile
#define TPB 2                  // tiles per block (serial)
#define TN 128                 // codes per k-chunk
#define CC 32                  // channels per stage
#define NTHREADS 128           // 16 tx (codes) x 8 ty (pixel rows), 4 px per row
#define NKC 8                  // k-chunks
#define NCC 8                  // c-chunks
#define TILE_STAGES (NKC * NCC)        // 64
#define NSTAGES (TPB * TILE_STAGES)    // 128 per block

#define ZS_F   (CC * TM)       // 1024 floats (4KB)
#define WS_F   (CC * TN)       // 4096 floats (16KB)
#define STAGE_F (ZS_F + WS_F)  // 5120 floats (20KB)
#define SMEM_BYTES (2 * STAGE_F * 4)   // 40960

// Normalized codebook: row-major (gather) and stage-packed (GEMM loads)
__device__ float g_wn[K_CODES * C_DIM];   // [k][c]
__device__ float g_wp[C_DIM * K_CODES];   // [stage ss][c&31][k&127]

// ---------------------------------------------------------------------------
__device__ __forceinline__ unsigned long long dupf(float x) {
    unsigned long long r;
    asm("mov.b64 %0, {%1, %1};" : "=l"(r) : "f"(x));
    return r;
}
__device__ __forceinline__ void ffma2(unsigned long long& d,
                                      unsigned long long a,
                                      unsigned long long b) {
    asm("fma.rn.f32x2 %0, %1, %2, %0;" : "+l"(d) : "l"(a), "l"(b));
}
__device__ __forceinline__ void unpack2(unsigned long long v, float& lo, float& hi) {
    asm("mov.b64 {%0, %1}, %2;" : "=f"(lo), "=f"(hi) : "l"(v));
}
__device__ __forceinline__ unsigned int smem_u32(const void* p) {
    return (unsigned int)__cvta_generic_to_shared(p);
}
__device__ __forceinline__ void cp16(unsigned int dst, const void* src) {
    asm volatile("cp.async.cg.shared.global [%0], [%1], 16;" :: "r"(dst), "l"(src));
}
__device__ __forceinline__ void cp_commit() {
    asm volatile("cp.async.commit_group;");
}
template<int N>
__device__ __forceinline__ void cp_wait() {
    asm volatile("cp.async.wait_group %0;" :: "n"(N));
}

// ---------------------------------------------------------------------------
// Kernel 1: L2-normalize codebook rows -> g_wn row-major + g_wp stage-packed.
// stage ss = (k>>7)*8 + (c>>5); within stage: [c&31][k&127]
// ---------------------------------------------------------------------------
__global__ void vq_norm_weight_kernel(const float* __restrict__ w) {
    const int k = blockIdx.x;
    const int t = threadIdx.x;           // channel
    float v = w[k * C_DIM + t];
    float s = v * v;
    #pragma unroll
    for (int off = 16; off; off >>= 1)
        s += __shfl_xor_sync(0xffffffffu, s, off);
    __shared__ float ssum[8];
    if ((t & 31) == 0) ssum[t >> 5] = s;
    __syncthreads();
    float tot = ssum[0] + ssum[1] + ssum[2] + ssum[3]
              + ssum[4] + ssum[5] + ssum[6] + ssum[7];
    float den = fmaxf(sqrtf(tot), 1e-12f);
    float o = v / den;                   // full-precision fp32 divide (match jnp)
    g_wn[k * C_DIM + t] = o;
    int stage = ((k >> 7) << 3) + (t >> 5);
    g_wp[(stage << 12) + ((t & 31) << 7) + (k & 127)] = o;
}

// ---------------------------------------------------------------------------
// Kernel 2: argmax_k <z_n, w_k> + gather z_q.
// 512 blocks x 128 threads, each block does 2 pixel-tiles serially with the
// cp.async ring rolling across the tile boundary. One co-resident wave.
// ---------------------------------------------------------------------------
__global__ __launch_bounds__(NTHREADS, 4)
void vq_argmax_kernel(const float* __restrict__ z,
                      float* __restrict__ out,
                      int write_idx) {
    extern __shared__ float sm[];        // 2 * STAGE_F ring
    __shared__ int sbidx[TM];            // per-tile indices (separate from ring)

    const int tid = threadIdx.x;
    const int tx = tid & 15;             // code lane
    const int ty = tid >> 4;             // pixel row -> pixels ty*4..ty*4+3
    const int base0 = blockIdx.x * (TM * TPB);

    // ---- stage fill: all linear 16B cp.async. Global stage s in [0,128) ----
    auto fill = [&](int s) {
        float* buf = sm + (s & 1) * STAGE_F;
        const int ss  = s & (TILE_STAGES - 1);   // stage within tile
        const int ccI = ss & (NCC - 1);
        const int n0  = base0 + (s >> 6) * TM;   // tile = s>>6
        const int b   = n0 >> 10;
        const int hw0 = n0 & 1023;
        const float* zbase = z + (((size_t)b * C_DIM) << 10) + hw0;
        #pragma unroll
        for (int t = 0; t < 2; t++) {            // zs: 256 float4
            int i  = tid + t * NTHREADS;
            int c  = i >> 3;
            int p4 = i & 7;
            cp16(smem_u32(buf + i * 4),
                 zbase + (((size_t)(ccI * CC + c)) << 10) + p4 * 4);
        }
        const float* wsrc = g_wp + ((size_t)ss << 12);
        #pragma unroll
        for (int t = 0; t < 8; t++) {            // ws: 1024 float4
            int i = tid + t * NTHREADS;
            cp16(smem_u32(buf + ZS_F + i * 4), wsrc + i * 4);
        }
        cp_commit();
    };

    fill(0);

    int s = 0;
    for (int tile = 0; tile < TPB; tile++) {
        const int n0  = base0 + tile * TM;
        const int b   = n0 >> 10;
        const int hw0 = n0 & 1023;

        float rbv[4];
        int   rbi[4];
        #pragma unroll
        for (int i = 0; i < 4; i++) { rbv[i] = -CUDART_INF_F; rbi[i] = 0; }

        for (int kcI = 0; kcI < NKC; kcI++) {
            unsigned long long acc[4][4];    // [pixel][code-pair]
            #pragma unroll
            for (int i = 0; i < 4; i++)
                #pragma unroll
                for (int j = 0; j < 4; j++) acc[i][j] = 0ull;

            for (int ccI = 0; ccI < NCC; ccI++, s++) {
                cp_wait<0>();                 // fill(s) complete
                __syncthreads();              // everyone done computing s-1
                if (s + 1 < NSTAGES) fill(s + 1);   // overwrites buffer of s-1

                const float* zb = sm + (s & 1) * STAGE_F;
                const float* wb = zb + ZS_F;

                #pragma unroll 4
                for (int c = 0; c < CC; c++) {
                    float4 zv = *(const float4*)(zb + c * TM + (ty << 2));
                    const float* wr = wb + c * TN + (tx << 2);
                    ulonglong2 w0 = *(const ulonglong2*)wr;         // codes tx*4..+3
                    ulonglong2 w1 = *(const ulonglong2*)(wr + 64);  // codes 64+..
                    unsigned long long zp0 = dupf(zv.x);
                    unsigned long long zp1 = dupf(zv.y);
                    unsigned long long zp2 = dupf(zv.z);
                    unsigned long long zp3 = dupf(zv.w);
                    ffma2(acc[0][0], zp0, w0.x); ffma2(acc[0][1], zp0, w0.y);
                    ffma2(acc[0][2], zp0, w1.x); ffma2(acc[0][3], zp0, w1.y);
                    ffma2(acc[1][0], zp1, w0.x); ffma2(acc[1][1], zp1, w0.y);
                    ffma2(acc[1][2], zp1, w1.x); ffma2(acc[1][3], zp1, w1.y);
                    ffma2(acc[2][0], zp2, w0.x); ffma2(acc[2][1], zp2, w0.y);
                    ffma2(acc[2][2], zp2, w1.x); ffma2(acc[2][3], zp2, w1.y);
                    ffma2(acc[3][0], zp3, w0.x); ffma2(acc[3][1], zp3, w0.y);
                    ffma2(acc[3][2], zp3, w1.x); ffma2(acc[3][3], zp3, w1.y);
                }
            }

            // ---- chunk argmax (increasing-k scan, strict >: first max wins) ----
            const int kc = kcI * TN;
            #pragma unroll
            for (int i = 0; i < 4; i++) {
                float bv = -CUDART_INF_F;
                int   bk = 0;
                #pragma unroll
                for (int j = 0; j < 4; j++) {
                    float lo, hi;
                    unpack2(acc[i][j], lo, hi);
                    int k0 = kc + (tx << 2) + ((j >> 1) << 6) + ((j & 1) << 1);
                    if (lo > bv) { bv = lo; bk = k0; }
                    if (hi > bv) { bv = hi; bk = k0 + 1; }
                }
                #pragma unroll
                for (int off = 8; off; off >>= 1) {      // across 16 tx lanes
                    float ov = __shfl_xor_sync(0xffffffffu, bv, off);
                    int   ok = __shfl_xor_sync(0xffffffffu, bk, off);
                    if (ov > bv || (ov == bv && ok < bk)) { bv = ov; bk = ok; }
                }
                if (bv > rbv[i]) { rbv[i] = bv; rbi[i] = bk; }   // later kc strictly >
            }
        }

        // ---- per-tile epilogue (overlaps with in-flight prefetch of next tile) ----
        if (tx == 0) {
            #pragma unroll
            for (int i = 0; i < 4; i++) sbidx[(ty << 2) + i] = rbi[i];
        }
        __syncthreads();

        // write z_q: out[b][c][hw0+p] = g_wn[idx[p]][c], coalesced over p
        #pragma unroll 4
        for (int i = tid; i < C_DIM * TM; i += NTHREADS) {
            int p = i & (TM - 1);
            int c = i >> 5;
            out[(((size_t)(b * C_DIM + c)) << 10) + hw0 + p] =
                g_wn[(size_t)sbidx[p] * C_DIM + c];
        }
        if (write_idx && tid < TM) {
            out[ZQ_ELEMS + n0 + tid] = (float)sbidx[tid];
        }
        __syncthreads();   // sbidx consumed before next tile overwrites it
    }
}

// ---------------------------------------------------------------------------
extern "C" void kernel_launch(void* const* d_in, const int* in_sizes, int n_in,
                              void* d_out, int out_size) {
    const float* z_e    = (const float*)d_in[0];
    const float* weight = (const float*)d_in[1];
    float* out = (float*)d_out;

    const int write_idx = (out_size >= ZQ_ELEMS + N_PIX) ? 1 : 0;

    static int init_done = 0;
    if (!init_done) {
        cudaFuncSetAttribute(vq_argmax_kernel,
                             cudaFuncAttributeMaxDynamicSharedMemorySize,
                             SMEM_BYTES);
        cudaFuncSetAttribute(vq_argmax_kernel,
                             cudaFuncAttributePreferredSharedMemoryCarveout,
                             cudaSharedmemCarveoutMaxShared);
        init_done = 1;
    }

    vq_norm_weight_kernel<<<K_CODES, C_DIM>>>(weight);
    vq_argmax_kernel<<<N_PIX / (TM * TPB), NTHREADS, SMEM_BYTES>>>(z_e, out, write_idx);
}

// round 10
// speedup vs baseline: 1.1291x; 1.1291x over previous
#include <cuda_runtime.h>
#include <math_constants.h>

// Problem constants
#define K_CODES 1024
#define C_DIM   256
#define N_PIX   32768
#define ZQ_ELEMS 8388608       // 32*256*32*32

// Tiling
#define TM 32                  // pixels per block
#define TN 256                 // codes per k-chunk
#define CC 16                  // channels per stage
#define NTHREADS 128           // 16 tx (codes) x 8 ty (pixel rows), 4 px per row
#define NKC 4                  // k-chunks (1024/256)
#define NCC 16                 // c-chunks (256/16)
#define NSTAGES (NKC * NCC)    // 64

#define ZS_F   (CC * TM)       // 512 floats  (2KB)
#define WS_F   (CC * TN)       // 4096 floats (16KB)
#define STAGE_F (ZS_F + WS_F)  // 4608 floats (18KB)
#define SMEM_BYTES (2 * STAGE_F * 4)   // 36864

// Normalized codebook: row-major (gather) and stage-packed (GEMM loads)
__device__ float g_wn[K_CODES * C_DIM];   // [k][c]
__device__ float g_wp[C_DIM * K_CODES];   // [stage ss][c&15][k&255]

// ---------------------------------------------------------------------------
__device__ __forceinline__ unsigned long long dupf(float x) {
    unsigned long long r;
    asm("mov.b64 %0, {%1, %1};" : "=l"(r) : "f"(x));
    return r;
}
__device__ __forceinline__ void ffma2(unsigned long long& d,
                                      unsigned long long a,
                                      unsigned long long b) {
    asm("fma.rn.f32x2 %0, %1, %2, %0;" : "+l"(d) : "l"(a), "l"(b));
}
__device__ __forceinline__ void unpack2(unsigned long long v, float& lo, float& hi) {
    asm("mov.b64 {%0, %1}, %2;" : "=f"(lo), "=f"(hi) : "l"(v));
}
__device__ __forceinline__ unsigned int smem_u32(const void* p) {
    return (unsigned int)__cvta_generic_to_shared(p);
}
__device__ __forceinline__ void cp16(unsigned int dst, const void* src) {
    asm volatile("cp.async.cg.shared.global [%0], [%1], 16;" :: "r"(dst), "l"(src));
}
__device__ __forceinline__ void cp_commit() {
    asm volatile("cp.async.commit_group;");
}
template<int N>
__device__ __forceinline__ void cp_wait() {
    asm volatile("cp.async.wait_group %0;" :: "n"(N));
}

// ---------------------------------------------------------------------------
// Kernel 1: L2-normalize codebook rows -> g_wn row-major + g_wp stage-packed.
// stage ss = (k>>8)*16 + (c>>4); within stage: [c&15][k&255]
// ---------------------------------------------------------------------------
__global__ void vq_norm_weight_kernel(const float* __restrict__ w) {
    const int k = blockIdx.x;
    const int t = threadIdx.x;           // channel
    float v = w[k * C_DIM + t];
    float s = v * v;
    #pragma unroll
    for (int off = 16; off; off >>= 1)
        s += __shfl_xor_sync(0xffffffffu, s, off);
    __shared__ float ssum[8];
    if ((t & 31) == 0) ssum[t >> 5] = s;
    __syncthreads();
    float tot = ssum[0] + ssum[1] + ssum[2] + ssum[3]
              + ssum[4] + ssum[5] + ssum[6] + ssum[7];
    float den = fmaxf(sqrtf(tot), 1e-12f);
    float o = v / den;                   // full-precision fp32 divide (match jnp)
    g_wn[k * C_DIM + t] = o;
    int stage = ((k >> 8) << 4) + (t >> 4);
    g_wp[((size_t)stage << 12) + ((t & 15) << 8) + (k & 255)] = o;
}

// ---------------------------------------------------------------------------
// Kernel 2: argmax_k <z_n, w_k> + gather z_q.
// 1024 blocks x 128 threads; 36KB dynamic smem (2-stage ring) -> 5 blocks/SM.
// ---------------------------------------------------------------------------
__global__ __launch_bounds__(NTHREADS, 5)
void vq_argmax_kernel(const float* __restrict__ z,
                      float* __restrict__ out,
                      int write_idx) {
    extern __shared__ float sm[];        // 2 * STAGE_F

    const int tid = threadIdx.x;
    const int tx = tid & 15;             // code lane
    const int ty = tid >> 4;             // pixel row -> pixels ty*4..ty*4+3
    const int n0 = blockIdx.x * TM;
    const int b   = n0 >> 10;
    const int hw0 = n0 & 1023;
    const float* zbase = z + (((size_t)b * C_DIM) << 10) + hw0;

    // ---- stage fill: all linear 16B cp.async ----
    auto fill = [&](int s) {
        float* buf = sm + (s & 1) * STAGE_F;
        const int ccI = s & (NCC - 1);
        {   // zs: 128 float4 (one per thread): [c 16][p 32]
            int c  = tid >> 3;
            int p4 = tid & 7;
            cp16(smem_u32(buf + tid * 4),
                 zbase + (((size_t)(ccI * CC + c)) << 10) + p4 * 4);
        }
        const float* wsrc = g_wp + ((size_t)s << 12);
        #pragma unroll
        for (int t = 0; t < 8; t++) {            // ws: 1024 float4
            int i = tid + t * NTHREADS;
            cp16(smem_u32(buf + ZS_F + i * 4), wsrc + i * 4);
        }
        cp_commit();
    };

    fill(0);

    float rbv[4];
    int   rbi[4];
    #pragma unroll
    for (int i = 0; i < 4; i++) { rbv[i] = -CUDART_INF_F; rbi[i] = 0; }

    int s = 0;
    for (int kcI = 0; kcI < NKC; kcI++) {
        unsigned long long acc[4][8];    // [pixel][q*2+j], codes kc+q*64+tx*4+j*2(+1)
        #pragma unroll
        for (int i = 0; i < 4; i++)
            #pragma unroll
            for (int j = 0; j < 8; j++) acc[i][j] = 0ull;

        for (int ccI = 0; ccI < NCC; ccI++, s++) {
            cp_wait<0>();                 // fill(s) complete
            __syncthreads();              // everyone done computing s-1
            if (s + 1 < NSTAGES) fill(s + 1);   // overwrites buffer of s-1

            const float* zb = sm + (s & 1) * STAGE_F;
            const float* wb = zb + ZS_F;

            #pragma unroll 2
            for (int c = 0; c < CC; c++) {
                float4 zv = *(const float4*)(zb + c * TM + (ty << 2));
                unsigned long long zp0 = dupf(zv.x);
                unsigned long long zp1 = dupf(zv.y);
                unsigned long long zp2 = dupf(zv.z);
                unsigned long long zp3 = dupf(zv.w);
                const float* wr = wb + c * TN + (tx << 2);
                #pragma unroll
                for (int q = 0; q < 4; q++) {
                    ulonglong2 w = *(const ulonglong2*)(wr + q * 64);
                    ffma2(acc[0][q*2+0], zp0, w.x); ffma2(acc[0][q*2+1], zp0, w.y);
                    ffma2(acc[1][q*2+0], zp1, w.x); ffma2(acc[1][q*2+1], zp1, w.y);
                    ffma2(acc[2][q*2+0], zp2, w.x); ffma2(acc[2][q*2+1], zp2, w.y);
                    ffma2(acc[3][q*2+0], zp3, w.x); ffma2(acc[3][q*2+1], zp3, w.y);
                }
            }
        }

        // ---- chunk argmax (increasing-k scan, strict >: first max wins) ----
        const int kc = kcI * TN;
        #pragma unroll
        for (int i = 0; i < 4; i++) {
            float bv = -CUDART_INF_F;
            int   bk = 0;
            #pragma unroll
            for (int q = 0; q < 4; q++) {
                #pragma unroll
                for (int j = 0; j < 2; j++) {
                    float lo, hi;
                    unpack2(acc[i][q*2+j], lo, hi);
                    int k0 = kc + q * 64 + (tx << 2) + (j << 1);
                    if (lo > bv) { bv = lo; bk = k0; }
                    if (hi > bv) { bv = hi; bk = k0 + 1; }
                }
            }
            #pragma unroll
            for (int off = 8; off; off >>= 1) {      // across 16 tx lanes
                float ov = __shfl_xor_sync(0xffffffffu, bv, off);
                int   ok = __shfl_xor_sync(0xffffffffu, bk, off);
                if (ov > bv || (ov == bv && ok < bk)) { bv = ov; bk = ok; }
            }
            if (bv > rbv[i]) { rbv[i] = bv; rbi[i] = bk; }   // later kc strictly >
        }
    }

    // ---- publish per-pixel indices (ring idle now; reuse as int buffer) ----
    __syncthreads();
    int* sbidx = (int*)sm;
    if (tx == 0) {
        #pragma unroll
        for (int i = 0; i < 4; i++) sbidx[(ty << 2) + i] = rbi[i];
    }
    __syncthreads();

    // ---- write z_q: out[b][c][hw0+p] = g_wn[idx[p]][c], coalesced over p ----
    #pragma unroll 4
    for (int i = tid; i < C_DIM * TM; i += NTHREADS) {
        int p = i & (TM - 1);
        int c = i >> 5;
        out[(((size_t)(b * C_DIM + c)) << 10) + hw0 + p] =
            g_wn[(size_t)sbidx[p] * C_DIM + c];
    }
    if (write_idx && tid < TM) {
        out[ZQ_ELEMS + n0 + tid] = (float)sbidx[tid];
    }
}

// ---------------------------------------------------------------------------
extern "C" void kernel_launch(void* const* d_in, const int* in_sizes, int n_in,
                              void* d_out, int out_size) {
    const float* z_e    = (const float*)d_in[0];
    const float* weight = (const float*)d_in[1];
    float* out = (float*)d_out;

    const int write_idx = (out_size >= ZQ_ELEMS + N_PIX) ? 1 : 0;

    static int init_done = 0;
    if (!init_done) {
        cudaFuncSetAttribute(vq_argmax_kernel,
                             cudaFuncAttributeMaxDynamicSharedMemorySize,
                             SMEM_BYTES);
        cudaFuncSetAttribute(vq_argmax_kernel,
                             cudaFuncAttributePreferredSharedMemoryCarveout,
                             cudaSharedmemCarveoutMaxShared);
        init_done = 1;
    }

    vq_norm_weight_kernel<<<K_CODES, C_DIM>>>(weight);
    vq_argmax_kernel<<<N_PIX / TM, NTHREADS, SMEM_BYTES>>>(z_e, out, write_idx);
}

// round 11
// speedup vs baseline: 1.1312x; 1.0018x over previous
#include <cuda_runtime.h>
#include <math_constants.h>

// Problem constants
#define K_CODES 1024
#define C_DIM   256
#define N_PIX   32768
#define ZQ_ELEMS 8388608       // 32*256*32*32

// Tiling
#define TM 32                  // pixels per block
#define TN 256                 // codes per k-chunk
#define CC 16                  // channels per stage
#define NTHREADS 128           // 16 tx (codes) x 8 ty (pixel rows), 4 px per row
#define NKC 4                  // k-chunks (1024/256)
#define NCC 16                 // c-chunks (256/16)
#define NSTAGES (NKC * NCC)    // 64

#define ZS_F   (CC * TM)       // 512 floats  (2KB)
#define WS_F   (CC * TN)       // 4096 floats (16KB)
#define STAGE_F (ZS_F + WS_F)  // 4608 floats (18KB)
#define SMEM_BYTES (2 * STAGE_F * 4)   // 36864

// Normalized codebook: row-major (gather) and stage-packed (GEMM loads)
__device__ float g_wn[K_CODES * C_DIM];   // [k][c]
__device__ float g_wp[C_DIM * K_CODES];   // [stage ss][c&15][k&255]

// ---------------------------------------------------------------------------
__device__ __forceinline__ unsigned long long dupf(float x) {
    unsigned long long r;
    asm("mov.b64 %0, {%1, %1};" : "=l"(r) : "f"(x));
    return r;
}
__device__ __forceinline__ void ffma2(unsigned long long& d,
                                      unsigned long long a,
                                      unsigned long long b) {
    asm("fma.rn.f32x2 %0, %1, %2, %0;" : "+l"(d) : "l"(a), "l"(b));
}
__device__ __forceinline__ void unpack2(unsigned long long v, float& lo, float& hi) {
    asm("mov.b64 {%0, %1}, %2;" : "=f"(lo), "=f"(hi) : "l"(v));
}
__device__ __forceinline__ unsigned int smem_u32(const void* p) {
    return (unsigned int)__cvta_generic_to_shared(p);
}
__device__ __forceinline__ void cp16(unsigned int dst, const void* src) {
    asm volatile("cp.async.cg.shared.global [%0], [%1], 16;" :: "r"(dst), "l"(src));
}
__device__ __forceinline__ void cp_commit() {
    asm volatile("cp.async.commit_group;");
}
template<int N>
__device__ __forceinline__ void cp_wait() {
    asm volatile("cp.async.wait_group %0;" :: "n"(N));
}

// ---------------------------------------------------------------------------
// Kernel 1: L2-normalize codebook rows -> g_wn row-major + g_wp stage-packed.
// stage ss = (k>>8)*16 + (c>>4); within stage: [c&15][k&255]
// ---------------------------------------------------------------------------
__global__ void vq_norm_weight_kernel(const float* __restrict__ w) {
    const int k = blockIdx.x;
    const int t = threadIdx.x;           // channel
    float v = w[k * C_DIM + t];
    float s = v * v;
    #pragma unroll
    for (int off = 16; off; off >>= 1)
        s += __shfl_xor_sync(0xffffffffu, s, off);
    __shared__ float ssum[8];
    if ((t & 31) == 0) ssum[t >> 5] = s;
    __syncthreads();
    float tot = ssum[0] + ssum[1] + ssum[2] + ssum[3]
              + ssum[4] + ssum[5] + ssum[6] + ssum[7];
    float den = fmaxf(sqrtf(tot), 1e-12f);
    float o = v / den;                   // full-precision fp32 divide (match jnp)
    g_wn[k * C_DIM + t] = o;
    int stage = ((k >> 8) << 4) + (t >> 4);
    g_wp[((size_t)stage << 12) + ((t & 15) << 8) + (k & 255)] = o;
}

// ---------------------------------------------------------------------------
// Kernel 2: argmax_k <z_n, w_k> + gather z_q.
// 1024 blocks x 128 threads; 36KB dynamic smem (2-stage ring) -> 5 blocks/SM.
// ---------------------------------------------------------------------------
__global__ __launch_bounds__(NTHREADS, 5)
void vq_argmax_kernel(const float* __restrict__ z,
                      float* __restrict__ out,
                      int write_idx) {
    extern __shared__ float sm[];        // 2 * STAGE_F

    const int tid = threadIdx.x;
    const int tx = tid & 15;             // code lane
    const int ty = tid >> 4;             // pixel row -> pixels ty*4..ty*4+3
    const int n0 = blockIdx.x * TM;
    const int b   = n0 >> 10;
    const int hw0 = n0 & 1023;
    const float* zbase = z + (((size_t)b * C_DIM) << 10) + hw0;

    // ---- stage fill: all linear 16B cp.async ----
    auto fill = [&](int s) {
        float* buf = sm + (s & 1) * STAGE_F;
        const int ccI = s & (NCC - 1);
        {   // zs: 128 float4 (one per thread): [c 16][p 32]
            int c  = tid >> 3;
            int p4 = tid & 7;
            cp16(smem_u32(buf + tid * 4),
                 zbase + (((size_t)(ccI * CC + c)) << 10) + p4 * 4);
        }
        const float* wsrc = g_wp + ((size_t)s << 12);
        #pragma unroll
        for (int t = 0; t < 8; t++) {            // ws: 1024 float4
            int i = tid + t * NTHREADS;
            cp16(smem_u32(buf + ZS_F + i * 4), wsrc + i * 4);
        }
        cp_commit();
    };

    fill(0);

    float rbv[4];
    int   rbi[4];
    #pragma unroll
    for (int i = 0; i < 4; i++) { rbv[i] = -CUDART_INF_F; rbi[i] = 0; }

    int s = 0;
    for (int kcI = 0; kcI < NKC; kcI++) {
        unsigned long long acc[4][8];    // [pixel][q*2+j], codes kc+q*64+tx*4+j*2(+1)
        #pragma unroll
        for (int i = 0; i < 4; i++)
            #pragma unroll
            for (int j = 0; j < 8; j++) acc[i][j] = 0ull;

        for (int ccI = 0; ccI < NCC; ccI++, s++) {
            cp_wait<0>();                 // fill(s) complete
            __syncthreads();              // everyone done computing s-1
            if (s + 1 < NSTAGES) fill(s + 1);   // overwrites buffer of s-1

            const float* zb = sm + (s & 1) * STAGE_F;
            const float* wb = zb + ZS_F;

            #pragma unroll 2
            for (int c = 0; c < CC; c++) {
                float4 zv = *(const float4*)(zb + c * TM + (ty << 2));
                unsigned long long zp0 = dupf(zv.x);
                unsigned long long zp1 = dupf(zv.y);
                unsigned long long zp2 = dupf(zv.z);
                unsigned long long zp3 = dupf(zv.w);
                const float* wr = wb + c * TN + (tx << 2);
                #pragma unroll
                for (int q = 0; q < 4; q++) {
                    ulonglong2 w = *(const ulonglong2*)(wr + q * 64);
                    ffma2(acc[0][q*2+0], zp0, w.x); ffma2(acc[0][q*2+1], zp0, w.y);
                    ffma2(acc[1][q*2+0], zp1, w.x); ffma2(acc[1][q*2+1], zp1, w.y);
                    ffma2(acc[2][q*2+0], zp2, w.x); ffma2(acc[2][q*2+1], zp2, w.y);
                    ffma2(acc[3][q*2+0], zp3, w.x); ffma2(acc[3][q*2+1], zp3, w.y);
                }
            }
        }

        // ---- chunk argmax (increasing-k scan, strict >: first max wins) ----
        const int kc = kcI * TN;
        #pragma unroll
        for (int i = 0; i < 4; i++) {
            float bv = -CUDART_INF_F;
            int   bk = 0;
            #pragma unroll
            for (int q = 0; q < 4; q++) {
                #pragma unroll
                for (int j = 0; j < 2; j++) {
                    float lo, hi;
                    unpack2(acc[i][q*2+j], lo, hi);
                    int k0 = kc + q * 64 + (tx << 2) + (j << 1);
                    if (lo > bv) { bv = lo; bk = k0; }
                    if (hi > bv) { bv = hi; bk = k0 + 1; }
                }
            }
            #pragma unroll
            for (int off = 8; off; off >>= 1) {      // across 16 tx lanes
                float ov = __shfl_xor_sync(0xffffffffu, bv, off);
                int   ok = __shfl_xor_sync(0xffffffffu, bk, off);
                if (ov > bv || (ov == bv && ok < bk)) { bv = ov; bk = ok; }
            }
            if (bv > rbv[i]) { rbv[i] = bv; rbi[i] = bk; }   // later kc strictly >
        }
    }

    // ---- publish per-pixel indices (ring idle now; reuse as int buffer) ----
    __syncthreads();
    int* sbidx = (int*)sm;
    if (tx == 0) {
        #pragma unroll
        for (int i = 0; i < 4; i++) sbidx[(ty << 2) + i] = rbi[i];
    }
    __syncthreads();

    // ---- write z_q: out[b][c][hw0+p] = g_wn[idx[p]][c], coalesced over p ----
    #pragma unroll 4
    for (int i = tid; i < C_DIM * TM; i += NTHREADS) {
        int p = i & (TM - 1);
        int c = i >> 5;
        out[(((size_t)(b * C_DIM + c)) << 10) + hw0 + p] =
            g_wn[(size_t)sbidx[p] * C_DIM + c];
    }
    if (write_idx && tid < TM) {
        out[ZQ_ELEMS + n0 + tid] = (float)sbidx[tid];
    }
}

// ---------------------------------------------------------------------------
extern "C" void kernel_launch(void* const* d_in, const int* in_sizes, int n_in,
                              void* d_out, int out_size) {
    const float* z_e    = (const float*)d_in[0];
    const float* weight = (const float*)d_in[1];
    float* out = (float*)d_out;

    const int write_idx = (out_size >= ZQ_ELEMS + N_PIX) ? 1 : 0;

    static int init_done = 0;
    if (!init_done) {
        cudaFuncSetAttribute(vq_argmax_kernel,
                             cudaFuncAttributeMaxDynamicSharedMemorySize,
                             SMEM_BYTES);
        cudaFuncSetAttribute(vq_argmax_kernel,
                             cudaFuncAttributePreferredSharedMemoryCarveout,
                             cudaSharedmemCarveoutMaxShared);
        init_done = 1;
    }

    vq_norm_weight_kernel<<<K_CODES, C_DIM>>>(weight);
    vq_argmax_kernel<<<N_PIX / TM, NTHREADS, SMEM_BYTES>>>(z_e, out, write_idx);
}